// round 1
// baseline (speedup 1.0000x reference)
#include <cuda_runtime.h>

// Problem constants (from reference)
#define K_GENES 20000
#define N_GO    5000
#define BATCH   4096
#define CAP     2048            // per-column entry capacity (true max ~40; huge safety margin)
#define B4      (BATCH/4)       // 1024 float4 per gene row

// Scratch in device globals (allocation inside kernel_launch is forbidden)
__device__ float4 g_xT4  [(size_t)K_GENES * B4];   // x transposed: [gene][batch]
__device__ float4 g_outT4[(size_t)N_GO    * B4];   // out transposed: [go][batch]
__device__ int    g_cnt  [N_GO];
__device__ int    g_ei   [(size_t)N_GO * CAP];     // gene index per entry
__device__ float  g_ev   [(size_t)N_GO * CAP];     // weight*mask value per entry

// ---------------------------------------------------------------------------
// 1) zero per-column counters
__global__ void zero_cnt_kernel() {
    int t = blockIdx.x * blockDim.x + threadIdx.x;
    if (t < N_GO) g_cnt[t] = 0;
}

// ---------------------------------------------------------------------------
// 2) scan mask, append (gene, w*m) to each column's list.
//    mask is 99.92% zero -> the hot loop is a pure float4 stream of the mask.
__global__ void build_entries_kernel(const float* __restrict__ w,
                                     const float* __restrict__ m) {
    const float4* m4 = (const float4*)m;
    const long total4 = (long)K_GENES * N_GO / 4;
    long stride = (long)gridDim.x * blockDim.x;
    for (long idx = (long)blockIdx.x * blockDim.x + threadIdx.x; idx < total4; idx += stride) {
        float4 mv = __ldg(m4 + idx);
        if (mv.x != 0.f || mv.y != 0.f || mv.z != 0.f || mv.w != 0.f) {
            float lane[4] = {mv.x, mv.y, mv.z, mv.w};
            long base = idx * 4;
            #pragma unroll
            for (int c = 0; c < 4; c++) {
                if (lane[c] != 0.f) {
                    long lin = base + c;
                    int i = (int)(lin / N_GO);
                    int j = (int)(lin - (long)i * N_GO);
                    float wv = __ldg(w + lin) * lane[c];
                    int pos = atomicAdd(&g_cnt[j], 1);
                    if (pos < CAP) {
                        g_ei[(size_t)j * CAP + pos] = i;
                        g_ev[(size_t)j * CAP + pos] = wv;
                    }
                }
            }
        }
    }
}

// ---------------------------------------------------------------------------
// 3) transpose x [4096, 20000] -> g_xT [20000, 4096]  (both dims /32)
__global__ void transpose_x_kernel(const float* __restrict__ in) {
    __shared__ float tile[32][33];
    float* out = (float*)g_xT4;
    int c  = blockIdx.x * 32 + threadIdx.x;   // gene
    int r0 = blockIdx.y * 32;                 // batch base
    #pragma unroll
    for (int k = threadIdx.y; k < 32; k += 8) {
        tile[k][threadIdx.x] = in[(size_t)(r0 + k) * K_GENES + c];
    }
    __syncthreads();
    int r  = r0 + threadIdx.x;                // batch (now contiguous on write)
    int c0 = blockIdx.x * 32;
    #pragma unroll
    for (int k = threadIdx.y; k < 32; k += 8) {
        out[(size_t)(c0 + k) * BATCH + r] = tile[threadIdx.x][k];
    }
}

// ---------------------------------------------------------------------------
// 4) per-column sparse accumulation: outT[j, :] = sum_e w_e * xT[i_e, :]
//    blockIdx.x = column j, blockIdx.y = batch chunk (1024 batch elems each)
//    Entries sorted by gene id first -> deterministic FP accumulation order.
__global__ void spmm_col_kernel() {
    __shared__ int   si[CAP];
    __shared__ float sv[CAP];
    int j = blockIdx.x;
    int n = min(g_cnt[j], CAP);

    for (int e = threadIdx.x; e < n; e += blockDim.x) {
        si[e] = g_ei[(size_t)j * CAP + e];
        sv[e] = g_ev[(size_t)j * CAP + e];
    }
    __syncthreads();

    // odd-even transposition sort by gene id (keys distinct within a column)
    for (int p = 0; p < n; p++) {
        for (int k = (p & 1) + 2 * threadIdx.x; k + 1 < n; k += 2 * blockDim.x) {
            if (si[k] > si[k + 1]) {
                int ti = si[k]; si[k] = si[k + 1]; si[k + 1] = ti;
                float tv = sv[k]; sv[k] = sv[k + 1]; sv[k + 1] = tv;
            }
        }
        __syncthreads();
    }

    int t = threadIdx.x;                  // 256 threads, each owns one float4
    int chunk_off = blockIdx.y * 256;     // 4 chunks of 256 float4 = 1024 floats
    float4 acc = make_float4(0.f, 0.f, 0.f, 0.f);
    for (int e = 0; e < n; e++) {
        const float4* row = &g_xT4[(size_t)si[e] * B4 + chunk_off];
        float v = sv[e];
        float4 xv = __ldg(row + t);
        acc.x += xv.x * v; acc.y += xv.y * v;
        acc.z += xv.z * v; acc.w += xv.w * v;
    }
    g_outT4[(size_t)j * B4 + chunk_off + t] = acc;
}

// ---------------------------------------------------------------------------
// 5) transpose outT [5000, 4096] -> out [4096, 5000]
__global__ void transpose_out_kernel(float* __restrict__ out) {
    __shared__ float tile[32][33];
    const float* in = (const float*)g_outT4;
    int c  = blockIdx.x * 32 + threadIdx.x;   // batch index (contiguous read)
    int r0 = blockIdx.y * 32;                 // go-column base
    #pragma unroll
    for (int k = threadIdx.y; k < 32; k += 8) {
        int r = r0 + k;
        if (r < N_GO) tile[k][threadIdx.x] = in[(size_t)r * BATCH + c];
    }
    __syncthreads();
    int r  = r0 + threadIdx.x;                // go column (contiguous write)
    int c0 = blockIdx.x * 32;
    #pragma unroll
    for (int k = threadIdx.y; k < 32; k += 8) {
        if (r < N_GO) out[(size_t)(c0 + k) * N_GO + r] = tile[threadIdx.x][k];
    }
}

// ---------------------------------------------------------------------------
extern "C" void kernel_launch(void* const* d_in, const int* in_sizes, int n_in,
                              void* d_out, int out_size) {
    const float* x = (const float*)d_in[0];   // [4096, 20000]
    const float* w = (const float*)d_in[1];   // [20000, 5000]
    const float* m = (const float*)d_in[2];   // [20000, 5000]
    float* out = (float*)d_out;               // [4096, 5000]

    zero_cnt_kernel<<<(N_GO + 255) / 256, 256>>>();
    build_entries_kernel<<<4736, 256>>>(w, m);

    dim3 tb(32, 8);
    transpose_x_kernel<<<dim3(K_GENES / 32, BATCH / 32), tb>>>(x);

    spmm_col_kernel<<<dim3(N_GO, BATCH / 1024), 256>>>();

    transpose_out_kernel<<<dim3(BATCH / 32, (N_GO + 31) / 32), tb>>>(out);
}

// round 2
// speedup vs baseline: 1.1743x; 1.1743x over previous
#include <cuda_runtime.h>
#include <cuda_fp16.h>

// Problem constants (from reference)
#define K_GENES 20000
#define N_GO    5000
#define BATCH   4096
#define CAP     128            // per-column entry capacity (Poisson(16); max ~45)
#define JT      32             // columns per spmm block
#define BT      128            // batch elems per spmm block

// Scratch in device globals (allocation inside kernel_launch is forbidden)
__device__ __half g_xTh[(size_t)K_GENES * BATCH];  // x transposed, fp16: [gene][batch]
__device__ int    g_cnt[N_GO];
__device__ int    g_ei [(size_t)N_GO * CAP];       // gene index per entry
__device__ float  g_ev [(size_t)N_GO * CAP];       // weight*mask value per entry

// ---------------------------------------------------------------------------
// 1) zero per-column counters
__global__ void zero_cnt_kernel() {
    int t = blockIdx.x * blockDim.x + threadIdx.x;
    if (t < N_GO) g_cnt[t] = 0;
}

// ---------------------------------------------------------------------------
// 2) scan mask (99.92% zero -> pure float4 stream), append (gene, w*m) per column
__global__ void build_entries_kernel(const float* __restrict__ w,
                                     const float* __restrict__ m) {
    const float4* m4 = (const float4*)m;
    const long total4 = (long)K_GENES * N_GO / 4;
    long stride = (long)gridDim.x * blockDim.x;
    for (long idx = (long)blockIdx.x * blockDim.x + threadIdx.x; idx < total4; idx += stride) {
        float4 mv = __ldg(m4 + idx);
        if (mv.x != 0.f || mv.y != 0.f || mv.z != 0.f || mv.w != 0.f) {
            float lane[4] = {mv.x, mv.y, mv.z, mv.w};
            long base = idx * 4;
            #pragma unroll
            for (int c = 0; c < 4; c++) {
                if (lane[c] != 0.f) {
                    long lin = base + c;
                    int i = (int)(lin / N_GO);
                    int j = (int)(lin - (long)i * N_GO);
                    float wv = __ldg(w + lin) * lane[c];
                    int pos = atomicAdd(&g_cnt[j], 1);
                    if (pos < CAP) {
                        g_ei[(size_t)j * CAP + pos] = i;
                        g_ev[(size_t)j * CAP + pos] = wv;
                    }
                }
            }
        }
    }
}

// ---------------------------------------------------------------------------
// 3) transpose x [4096, 20000] fp32 -> g_xTh [20000, 4096] fp16
//    64-batch x 32-gene tiles; half2 writes (128B per warp store)
__global__ void transpose_x_h_kernel(const float* __restrict__ in) {
    __shared__ float tile[64][33];
    int c  = blockIdx.x * 32 + threadIdx.x;   // gene
    int r0 = blockIdx.y * 64;                 // batch base
    #pragma unroll
    for (int k = threadIdx.y; k < 64; k += 8) {
        tile[k][threadIdx.x] = in[(size_t)(r0 + k) * K_GENES + c];
    }
    __syncthreads();
    int c0 = blockIdx.x * 32;
    #pragma unroll
    for (int k = threadIdx.y; k < 32; k += 8) {
        __half2 v = __floats2half2_rn(tile[2 * threadIdx.x][k],
                                      tile[2 * threadIdx.x + 1][k]);
        *(__half2*)&g_xTh[(size_t)(c0 + k) * BATCH + r0 + 2 * threadIdx.x] = v;
    }
}

// ---------------------------------------------------------------------------
// 4) fused sparse accumulation + output write.
//    Block = (32 columns, 128 batch). Warp w owns 4 columns x 128 batch.
//    Entries sorted per column (deterministic FP order). Output staged through
//    smem and written coalesced to out[b, j] directly (no outT round-trip).
//    Grid is x-fastest over column tiles -> concurrent blocks share the batch
//    chunk -> per-wave gene working set ~5MB -> L2-resident reuse.
__global__ void spmm_fused_kernel(float* __restrict__ out) {
    __shared__ int   s_ei[8][CAP];
    __shared__ float s_ev[8][CAP];
    __shared__ float s_out[BT][JT + 1];

    int w    = threadIdx.x >> 5;
    int lane = threadIdx.x & 31;
    int b0   = blockIdx.y * BT;
    int jbase = blockIdx.x * JT + w * 4;

    float4 acc[4];
    #pragma unroll
    for (int cc = 0; cc < 4; cc++) acc[cc] = make_float4(0.f, 0.f, 0.f, 0.f);

    #pragma unroll
    for (int cc = 0; cc < 4; cc++) {
        int j = jbase + cc;
        int n = 0;
        if (j < N_GO) n = min(g_cnt[j], CAP);

        for (int e = lane; e < n; e += 32) {
            s_ei[w][e] = g_ei[(size_t)j * CAP + e];
            s_ev[w][e] = g_ev[(size_t)j * CAP + e];
        }
        __syncwarp();

        // odd-even transposition sort by gene id (deterministic accum order)
        for (int p = 0; p < n; p++) {
            for (int k = (p & 1) + 2 * lane; k + 1 < n; k += 64) {
                if (s_ei[w][k] > s_ei[w][k + 1]) {
                    int ti = s_ei[w][k]; s_ei[w][k] = s_ei[w][k + 1]; s_ei[w][k + 1] = ti;
                    float tv = s_ev[w][k]; s_ev[w][k] = s_ev[w][k + 1]; s_ev[w][k + 1] = tv;
                }
            }
            __syncwarp();
        }

        for (int e = 0; e < n; e++) {
            int   i = s_ei[w][e];
            float v = s_ev[w][e];
            const uint2* p = (const uint2*)(g_xTh + (size_t)i * BATCH + b0 + lane * 4);
            uint2 u = __ldg(p);
            __half2 h0 = *(__half2*)&u.x;
            __half2 h1 = *(__half2*)&u.y;
            float2 f0 = __half22float2(h0);
            float2 f1 = __half22float2(h1);
            acc[cc].x = fmaf(f0.x, v, acc[cc].x);
            acc[cc].y = fmaf(f0.y, v, acc[cc].y);
            acc[cc].z = fmaf(f1.x, v, acc[cc].z);
            acc[cc].w = fmaf(f1.y, v, acc[cc].w);
        }
    }

    // stage: thread (w, lane) holds batch rows lane*4..+3, cols w*4..w*4+3
    #pragma unroll
    for (int cc = 0; cc < 4; cc++) {
        s_out[lane * 4 + 0][w * 4 + cc] = acc[cc].x;
        s_out[lane * 4 + 1][w * 4 + cc] = acc[cc].y;
        s_out[lane * 4 + 2][w * 4 + cc] = acc[cc].z;
        s_out[lane * 4 + 3][w * 4 + cc] = acc[cc].w;
    }
    __syncthreads();

    // coalesced write: 128B per row segment out[b, j0..j0+31]
    int col = threadIdx.x & 31;
    int j   = blockIdx.x * JT + col;
    if (j < N_GO) {
        #pragma unroll
        for (int r = threadIdx.x >> 5; r < BT; r += 8) {
            out[(size_t)(b0 + r) * N_GO + j] = s_out[r][col];
        }
    }
}

// ---------------------------------------------------------------------------
extern "C" void kernel_launch(void* const* d_in, const int* in_sizes, int n_in,
                              void* d_out, int out_size) {
    const float* x = (const float*)d_in[0];   // [4096, 20000]
    const float* w = (const float*)d_in[1];   // [20000, 5000]
    const float* m = (const float*)d_in[2];   // [20000, 5000]
    float* out = (float*)d_out;               // [4096, 5000]

    zero_cnt_kernel<<<(N_GO + 255) / 256, 256>>>();
    build_entries_kernel<<<4736, 256>>>(w, m);

    transpose_x_h_kernel<<<dim3(K_GENES / 32, BATCH / 64), dim3(32, 8)>>>(x);

    spmm_fused_kernel<<<dim3((N_GO + JT - 1) / JT, BATCH / BT), 256>>>(out);
}

// round 3
// speedup vs baseline: 1.3448x; 1.1452x over previous
#include <cuda_runtime.h>
#include <cuda_fp16.h>

// Problem constants (from reference)
#define K_GENES 20000
#define N_GO    5000
#define BATCH   4096
#define CAP     128            // per-column entry capacity (Poisson(16); max ~50)
#define JT      32             // columns per spmm block
#define BT      256            // batch elems per spmm block

// Scratch in device globals (allocation inside kernel_launch is forbidden)
__device__ __half g_xTh[(size_t)K_GENES * BATCH];  // x transposed, fp16: [gene][batch]
__device__ int    g_cnt[N_GO];
__device__ int    g_ei [(size_t)N_GO * CAP];       // gene index per entry
__device__ float  g_ev [(size_t)N_GO * CAP];       // weight*mask value per entry

// ---------------------------------------------------------------------------
// 1) zero per-column counters
__global__ void zero_cnt_kernel() {
    int t = blockIdx.x * blockDim.x + threadIdx.x;
    if (t < N_GO) g_cnt[t] = 0;
}

// ---------------------------------------------------------------------------
// 2) scan mask (99.92% zero -> pure float4 stream), append (gene, w*m) per column
__global__ void build_entries_kernel(const float* __restrict__ w,
                                     const float* __restrict__ m) {
    const float4* m4 = (const float4*)m;
    const long total4 = (long)K_GENES * N_GO / 4;
    long stride = (long)gridDim.x * blockDim.x;
    for (long idx = (long)blockIdx.x * blockDim.x + threadIdx.x; idx < total4; idx += stride) {
        float4 mv = __ldg(m4 + idx);
        if (mv.x != 0.f || mv.y != 0.f || mv.z != 0.f || mv.w != 0.f) {
            float lane[4] = {mv.x, mv.y, mv.z, mv.w};
            long base = idx * 4;
            #pragma unroll
            for (int c = 0; c < 4; c++) {
                if (lane[c] != 0.f) {
                    long lin = base + c;
                    int i = (int)(lin / N_GO);
                    int j = (int)(lin - (long)i * N_GO);
                    float wv = __ldg(w + lin) * lane[c];
                    int pos = atomicAdd(&g_cnt[j], 1);
                    if (pos < CAP) {
                        g_ei[(size_t)j * CAP + pos] = i;
                        g_ev[(size_t)j * CAP + pos] = wv;
                    }
                }
            }
        }
    }
}

// ---------------------------------------------------------------------------
// 2b) sort each column's entry list by gene id ONCE (deterministic FP order
//     in spmm, independent of atomic append order). One warp per column.
__global__ void sort_entries_kernel() {
    __shared__ int   s_i[8][CAP];
    __shared__ float s_v[8][CAP];
    int w    = threadIdx.x >> 5;
    int lane = threadIdx.x & 31;
    int j    = blockIdx.x * 8 + w;
    if (j >= N_GO) return;
    int n = min(g_cnt[j], CAP);

    for (int e = lane; e < n; e += 32) {
        s_i[w][e] = g_ei[(size_t)j * CAP + e];
        s_v[w][e] = g_ev[(size_t)j * CAP + e];
    }
    __syncwarp();
    // odd-even transposition sort (gene ids distinct within a column)
    for (int p = 0; p < n; p++) {
        for (int k = (p & 1) + 2 * lane; k + 1 < n; k += 64) {
            if (s_i[w][k] > s_i[w][k + 1]) {
                int   ti = s_i[w][k]; s_i[w][k] = s_i[w][k + 1]; s_i[w][k + 1] = ti;
                float tv = s_v[w][k]; s_v[w][k] = s_v[w][k + 1]; s_v[w][k + 1] = tv;
            }
        }
        __syncwarp();
    }
    for (int e = lane; e < n; e += 32) {
        g_ei[(size_t)j * CAP + e] = s_i[w][e];
        g_ev[(size_t)j * CAP + e] = s_v[w][e];
    }
}

// ---------------------------------------------------------------------------
// 3) transpose x [4096, 20000] fp32 -> g_xTh [20000, 4096] fp16
__global__ void transpose_x_h_kernel(const float* __restrict__ in) {
    __shared__ float tile[64][33];
    int c  = blockIdx.x * 32 + threadIdx.x;   // gene
    int r0 = blockIdx.y * 64;                 // batch base
    #pragma unroll
    for (int k = threadIdx.y; k < 64; k += 8) {
        tile[k][threadIdx.x] = in[(size_t)(r0 + k) * K_GENES + c];
    }
    __syncthreads();
    int c0 = blockIdx.x * 32;
    #pragma unroll
    for (int k = threadIdx.y; k < 32; k += 8) {
        __half2 v = __floats2half2_rn(tile[2 * threadIdx.x][k],
                                      tile[2 * threadIdx.x + 1][k]);
        *(__half2*)&g_xTh[(size_t)(c0 + k) * BATCH + r0 + 2 * threadIdx.x] = v;
    }
}

// ---------------------------------------------------------------------------
// 4) fused sparse accumulation + direct output write.
//    Block = (32 columns, 256 batch). Warp w owns 4 columns x 256 batch.
//    Lists are presorted; no per-block sort. Each lane loads uint4 (8 halves)
//    -> 8 FMAs per entry-iteration. Grid x-fastest over column tiles so the
//    per-wave gene working set (~10MB for one batch chunk) stays L2-resident.
__global__ void spmm_fused_kernel(float* __restrict__ out) {
    __shared__ int   s_ei[8][CAP];
    __shared__ float s_ev[8][CAP];
    __shared__ float s_out[BT][JT + 1];

    int w     = threadIdx.x >> 5;
    int lane  = threadIdx.x & 31;
    int b0    = blockIdx.y * BT;
    int jbase = blockIdx.x * JT + w * 4;

    #pragma unroll
    for (int cc = 0; cc < 4; cc++) {
        int j = jbase + cc;
        int n = 0;
        if (j < N_GO) n = min(g_cnt[j], CAP);

        for (int e = lane; e < n; e += 32) {
            s_ei[w][e] = g_ei[(size_t)j * CAP + e];
            s_ev[w][e] = g_ev[(size_t)j * CAP + e];
        }
        __syncwarp();

        float acc[8];
        #pragma unroll
        for (int q = 0; q < 8; q++) acc[q] = 0.f;

        const __half* xb = g_xTh + b0 + lane * 8;
        for (int e = 0; e < n; e++) {
            int   i = s_ei[w][e];
            float v = s_ev[w][e];
            uint4 u = __ldg((const uint4*)(xb + (size_t)i * BATCH));
            __half2 h0 = *(__half2*)&u.x;
            __half2 h1 = *(__half2*)&u.y;
            __half2 h2 = *(__half2*)&u.z;
            __half2 h3 = *(__half2*)&u.w;
            float2 f0 = __half22float2(h0);
            float2 f1 = __half22float2(h1);
            float2 f2 = __half22float2(h2);
            float2 f3 = __half22float2(h3);
            acc[0] = fmaf(f0.x, v, acc[0]);
            acc[1] = fmaf(f0.y, v, acc[1]);
            acc[2] = fmaf(f1.x, v, acc[2]);
            acc[3] = fmaf(f1.y, v, acc[3]);
            acc[4] = fmaf(f2.x, v, acc[4]);
            acc[5] = fmaf(f2.y, v, acc[5]);
            acc[6] = fmaf(f3.x, v, acc[6]);
            acc[7] = fmaf(f3.y, v, acc[7]);
        }
        __syncwarp();

        #pragma unroll
        for (int q = 0; q < 8; q++) {
            s_out[lane * 8 + q][w * 4 + cc] = acc[q];
        }
    }
    __syncthreads();

    // coalesced write: 128B per row segment out[b, j0..j0+31]
    int col = threadIdx.x & 31;
    int j   = blockIdx.x * JT + col;
    if (j < N_GO) {
        #pragma unroll 4
        for (int r = threadIdx.x >> 5; r < BT; r += 8) {
            out[(size_t)(b0 + r) * N_GO + j] = s_out[r][col];
        }
    }
}

// ---------------------------------------------------------------------------
extern "C" void kernel_launch(void* const* d_in, const int* in_sizes, int n_in,
                              void* d_out, int out_size) {
    const float* x = (const float*)d_in[0];   // [4096, 20000]
    const float* w = (const float*)d_in[1];   // [20000, 5000]
    const float* m = (const float*)d_in[2];   // [20000, 5000]
    float* out = (float*)d_out;               // [4096, 5000]

    zero_cnt_kernel<<<(N_GO + 255) / 256, 256>>>();
    build_entries_kernel<<<4736, 256>>>(w, m);
    sort_entries_kernel<<<(N_GO + 7) / 8, 256>>>();

    transpose_x_h_kernel<<<dim3(K_GENES / 32, BATCH / 64), dim3(32, 8)>>>(x);

    spmm_fused_kernel<<<dim3((N_GO + JT - 1) / JT, BATCH / BT), 256>>>(out);
}

// round 4
// speedup vs baseline: 1.7953x; 1.3350x over previous
#include <cuda_runtime.h>
#include <cuda_fp16.h>

// Problem constants (from reference)
#define K_GENES 20000
#define N_GO    5000
#define BATCH   4096
#define CAP     128            // per-column entry capacity (Poisson(16); max ~50)
#define JT      32             // columns per spmm block
#define BT      256            // batch elems per spmm block

// Scratch in device globals (allocation inside kernel_launch is forbidden)
__device__ __half g_xTh[(size_t)K_GENES * BATCH];  // x transposed, fp16: [gene][batch]
__device__ int    g_cnt[N_GO];
__device__ int    g_ei [(size_t)N_GO * CAP];       // gene index per entry
__device__ float  g_ev [(size_t)N_GO * CAP];       // weight*mask value per entry

// ---------------------------------------------------------------------------
// 1) zero per-column counters
__global__ void zero_cnt_kernel() {
    int t = blockIdx.x * blockDim.x + threadIdx.x;
    if (t < N_GO) g_cnt[t] = 0;
}

// ---------------------------------------------------------------------------
// 2) scan mask (99.92% zero -> pure float4 stream), append (gene, w*m) per column
__global__ void build_entries_kernel(const float* __restrict__ w,
                                     const float* __restrict__ m) {
    const float4* m4 = (const float4*)m;
    const long total4 = (long)K_GENES * N_GO / 4;
    long stride = (long)gridDim.x * blockDim.x;
    for (long idx = (long)blockIdx.x * blockDim.x + threadIdx.x; idx < total4; idx += stride) {
        float4 mv = __ldg(m4 + idx);
        if (mv.x != 0.f || mv.y != 0.f || mv.z != 0.f || mv.w != 0.f) {
            float lane[4] = {mv.x, mv.y, mv.z, mv.w};
            long base = idx * 4;
            #pragma unroll
            for (int c = 0; c < 4; c++) {
                if (lane[c] != 0.f) {
                    long lin = base + c;
                    int i = (int)(lin / N_GO);
                    int j = (int)(lin - (long)i * N_GO);
                    float wv = __ldg(w + lin) * lane[c];
                    int pos = atomicAdd(&g_cnt[j], 1);
                    if (pos < CAP) {
                        g_ei[(size_t)j * CAP + pos] = i;
                        g_ev[(size_t)j * CAP + pos] = wv;
                    }
                }
            }
        }
    }
}

// ---------------------------------------------------------------------------
// 2b) sort each column's entry list by gene id ONCE (deterministic FP order
//     in spmm, independent of atomic append order). One warp per column.
__global__ void sort_entries_kernel() {
    __shared__ int   s_i[8][CAP];
    __shared__ float s_v[8][CAP];
    int w    = threadIdx.x >> 5;
    int lane = threadIdx.x & 31;
    int j    = blockIdx.x * 8 + w;
    if (j >= N_GO) return;
    int n = min(g_cnt[j], CAP);

    for (int e = lane; e < n; e += 32) {
        s_i[w][e] = g_ei[(size_t)j * CAP + e];
        s_v[w][e] = g_ev[(size_t)j * CAP + e];
    }
    __syncwarp();
    // odd-even transposition sort (gene ids distinct within a column)
    for (int p = 0; p < n; p++) {
        for (int k = (p & 1) + 2 * lane; k + 1 < n; k += 64) {
            if (s_i[w][k] > s_i[w][k + 1]) {
                int   ti = s_i[w][k]; s_i[w][k] = s_i[w][k + 1]; s_i[w][k + 1] = ti;
                float tv = s_v[w][k]; s_v[w][k] = s_v[w][k + 1]; s_v[w][k + 1] = tv;
            }
        }
        __syncwarp();
    }
    for (int e = lane; e < n; e += 32) {
        g_ei[(size_t)j * CAP + e] = s_i[w][e];
        g_ev[(size_t)j * CAP + e] = s_v[w][e];
    }
}

// ---------------------------------------------------------------------------
// 3) transpose x [4096, 20000] fp32 -> g_xTh [20000, 4096] fp16
//    Tile: 64 genes x 64 batch. Read: float4 LDG.128 (4/thread).
//    Write: 8-batch gather from smem -> uint4 STG.128 (2/thread).
__global__ void transpose_x_h_kernel(const float* __restrict__ in) {
    __shared__ float tile[64][65];           // [batch][gene], odd stride
    int t  = threadIdx.x;                    // 256 threads
    int c0 = blockIdx.x * 64;                // gene base
    int r0 = blockIdx.y * 64;                // batch base

    // read phase: 4 passes x (16 float4-slots x 16 batch rows)
    int fx = t & 15;                         // float4 index within 64 genes
    int rr = t >> 4;                         // batch row 0..15
    bool cok = (c0 + 4 * fx) < K_GENES;      // tile-level gene bound
    #pragma unroll
    for (int p = 0; p < 4; p++) {
        int r = rr + 16 * p;
        if (cok) {
            float4 v = __ldg((const float4*)(in + (size_t)(r0 + r) * K_GENES + c0 + 4 * fx));
            tile[r][4 * fx + 0] = v.x;
            tile[r][4 * fx + 1] = v.y;
            tile[r][4 * fx + 2] = v.z;
            tile[r][4 * fx + 3] = v.w;
        }
    }
    __syncthreads();

    // write phase: 2 passes; thread covers (gene g, 8 batch vals) -> uint4
    int u  = t & 7;                          // uint4 index within 64 batch
    int gl = t >> 3;                         // gene 0..31
    #pragma unroll
    for (int p = 0; p < 2; p++) {
        int g = gl + 32 * p;
        if (c0 + g < K_GENES) {
            float f0 = tile[8 * u + 0][g], f1 = tile[8 * u + 1][g];
            float f2 = tile[8 * u + 2][g], f3 = tile[8 * u + 3][g];
            float f4 = tile[8 * u + 4][g], f5 = tile[8 * u + 5][g];
            float f6 = tile[8 * u + 6][g], f7 = tile[8 * u + 7][g];
            __half2 h0 = __floats2half2_rn(f0, f1);
            __half2 h1 = __floats2half2_rn(f2, f3);
            __half2 h2 = __floats2half2_rn(f4, f5);
            __half2 h3 = __floats2half2_rn(f6, f7);
            uint4 o;
            o.x = *(unsigned*)&h0; o.y = *(unsigned*)&h1;
            o.z = *(unsigned*)&h2; o.w = *(unsigned*)&h3;
            *(uint4*)&g_xTh[(size_t)(c0 + g) * BATCH + r0 + 8 * u] = o;
        }
    }
}

// ---------------------------------------------------------------------------
// 4) fused sparse accumulation + direct output write.
//    Block = (32 columns, 256 batch). Warp w owns 4 columns x 256 batch.
//    Lists are presorted; no per-block sort. Each lane loads uint4 (8 halves)
//    -> 8 FMAs per entry-iteration. Grid x-fastest over column tiles so the
//    per-wave gene working set stays L2-resident.
__global__ void spmm_fused_kernel(float* __restrict__ out) {
    __shared__ int   s_ei[8][CAP];
    __shared__ float s_ev[8][CAP];
    __shared__ float s_out[BT][JT + 1];

    int w     = threadIdx.x >> 5;
    int lane  = threadIdx.x & 31;
    int b0    = blockIdx.y * BT;
    int jbase = blockIdx.x * JT + w * 4;

    #pragma unroll
    for (int cc = 0; cc < 4; cc++) {
        int j = jbase + cc;
        int n = 0;
        if (j < N_GO) n = min(g_cnt[j], CAP);

        for (int e = lane; e < n; e += 32) {
            s_ei[w][e] = g_ei[(size_t)j * CAP + e];
            s_ev[w][e] = g_ev[(size_t)j * CAP + e];
        }
        __syncwarp();

        float acc[8];
        #pragma unroll
        for (int q = 0; q < 8; q++) acc[q] = 0.f;

        const __half* xb = g_xTh + b0 + lane * 8;
        for (int e = 0; e < n; e++) {
            int   i = s_ei[w][e];
            float v = s_ev[w][e];
            uint4 u = __ldg((const uint4*)(xb + (size_t)i * BATCH));
            float2 f0 = __half22float2(*(__half2*)&u.x);
            float2 f1 = __half22float2(*(__half2*)&u.y);
            float2 f2 = __half22float2(*(__half2*)&u.z);
            float2 f3 = __half22float2(*(__half2*)&u.w);
            acc[0] = fmaf(f0.x, v, acc[0]);
            acc[1] = fmaf(f0.y, v, acc[1]);
            acc[2] = fmaf(f1.x, v, acc[2]);
            acc[3] = fmaf(f1.y, v, acc[3]);
            acc[4] = fmaf(f2.x, v, acc[4]);
            acc[5] = fmaf(f2.y, v, acc[5]);
            acc[6] = fmaf(f3.x, v, acc[6]);
            acc[7] = fmaf(f3.y, v, acc[7]);
        }
        __syncwarp();

        #pragma unroll
        for (int q = 0; q < 8; q++) {
            s_out[lane * 8 + q][w * 4 + cc] = acc[q];
        }
    }
    __syncthreads();

    // coalesced write: 128B per row segment out[b, j0..j0+31]
    int col = threadIdx.x & 31;
    int j   = blockIdx.x * JT + col;
    if (j < N_GO) {
        #pragma unroll 4
        for (int r = threadIdx.x >> 5; r < BT; r += 8) {
            out[(size_t)(b0 + r) * N_GO + j] = s_out[r][col];
        }
    }
}

// ---------------------------------------------------------------------------
extern "C" void kernel_launch(void* const* d_in, const int* in_sizes, int n_in,
                              void* d_out, int out_size) {
    const float* x = (const float*)d_in[0];   // [4096, 20000]
    const float* w = (const float*)d_in[1];   // [20000, 5000]
    const float* m = (const float*)d_in[2];   // [20000, 5000]
    float* out = (float*)d_out;               // [4096, 5000]

    zero_cnt_kernel<<<(N_GO + 255) / 256, 256>>>();
    build_entries_kernel<<<4736, 256>>>(w, m);
    sort_entries_kernel<<<(N_GO + 7) / 8, 256>>>();

    transpose_x_h_kernel<<<dim3((K_GENES + 63) / 64, BATCH / 64), 256>>>(x);

    spmm_fused_kernel<<<dim3((N_GO + JT - 1) / JT, BATCH / BT), 256>>>(out);
}

// round 6
// speedup vs baseline: 1.8276x; 1.0180x over previous
#include <cuda_runtime.h>
#include <cuda_fp16.h>

// Problem constants (from reference)
#define K_GENES 20000
#define N_GO    5000
#define BATCH   4096
#define CAP     128            // per-column entry capacity (Poisson(16); max ~50)
#define JT      32             // columns per spmm block
#define BT      256            // batch elems per spmm block
#define CHUNK   1024           // batch rows per pipeline chunk (staging = 41MB, L2-resident)

// Scratch in device globals (allocation inside kernel_launch is forbidden)
// Staging buffer reused across chunks: [gene][CHUNK] fp16 -> stays in L2.
__device__ __half g_stage[(size_t)K_GENES * CHUNK];
__device__ int    g_cnt[N_GO];
__device__ int    g_ei [(size_t)N_GO * CAP];       // gene index per entry
__device__ float  g_ev [(size_t)N_GO * CAP];       // weight*mask value per entry

// ---------------------------------------------------------------------------
// 1) zero per-column counters
__global__ void zero_cnt_kernel() {
    int t = blockIdx.x * blockDim.x + threadIdx.x;
    if (t < N_GO) g_cnt[t] = 0;
}

// ---------------------------------------------------------------------------
// 2) scan mask (99.92% zero -> pure float4 stream, evict-first), append entries
__global__ void build_entries_kernel(const float* __restrict__ w,
                                     const float* __restrict__ m) {
    const float4* m4 = (const float4*)m;
    const long total4 = (long)K_GENES * N_GO / 4;
    long stride = (long)gridDim.x * blockDim.x;
    for (long idx = (long)blockIdx.x * blockDim.x + threadIdx.x; idx < total4; idx += stride) {
        float4 mv = __ldcs(m4 + idx);
        if (mv.x != 0.f || mv.y != 0.f || mv.z != 0.f || mv.w != 0.f) {
            float lane[4] = {mv.x, mv.y, mv.z, mv.w};
            long base = idx * 4;
            #pragma unroll
            for (int c = 0; c < 4; c++) {
                if (lane[c] != 0.f) {
                    long lin = base + c;
                    int i = (int)(lin / N_GO);
                    int j = (int)(lin - (long)i * N_GO);
                    float wv = __ldg(w + lin) * lane[c];
                    int pos = atomicAdd(&g_cnt[j], 1);
                    if (pos < CAP) {
                        g_ei[(size_t)j * CAP + pos] = i;
                        g_ev[(size_t)j * CAP + pos] = wv;
                    }
                }
            }
        }
    }
}

// ---------------------------------------------------------------------------
// 2b) sort each column's entry list by gene id ONCE (deterministic FP order).
__global__ void sort_entries_kernel() {
    __shared__ int   s_i[8][CAP];
    __shared__ float s_v[8][CAP];
    int w    = threadIdx.x >> 5;
    int lane = threadIdx.x & 31;
    int j    = blockIdx.x * 8 + w;
    if (j >= N_GO) return;
    int n = min(g_cnt[j], CAP);

    for (int e = lane; e < n; e += 32) {
        s_i[w][e] = g_ei[(size_t)j * CAP + e];
        s_v[w][e] = g_ev[(size_t)j * CAP + e];
    }
    __syncwarp();
    for (int p = 0; p < n; p++) {
        for (int k = (p & 1) + 2 * lane; k + 1 < n; k += 64) {
            if (s_i[w][k] > s_i[w][k + 1]) {
                int   ti = s_i[w][k]; s_i[w][k] = s_i[w][k + 1]; s_i[w][k + 1] = ti;
                float tv = s_v[w][k]; s_v[w][k] = s_v[w][k + 1]; s_v[w][k + 1] = tv;
            }
        }
        __syncwarp();
    }
    for (int e = lane; e < n; e += 32) {
        g_ei[(size_t)j * CAP + e] = s_i[w][e];
        g_ev[(size_t)j * CAP + e] = s_v[w][e];
    }
}

// ---------------------------------------------------------------------------
// 3) transpose one batch chunk of x -> g_stage [gene][CHUNK] fp16.
//    Tile 64 genes x 64 batch; float4 LDG.128 reads (evict-first: x is
//    stream-once), uint4 STG.128 staging writes (normal policy: want L2 hits).
__global__ void transpose_chunk_kernel(const float* __restrict__ in, int chunk) {
    __shared__ float tile[64][65];
    int t  = threadIdx.x;
    int c0 = blockIdx.x * 64;                // gene base
    int rl = blockIdx.y * 64;                // batch base within chunk
    int r0 = chunk * CHUNK + rl;             // global batch base

    int fx = t & 15;
    int rr = t >> 4;
    bool cok = (c0 + 4 * fx) < K_GENES;
    #pragma unroll
    for (int p = 0; p < 4; p++) {
        int r = rr + 16 * p;
        if (cok) {
            float4 v = __ldcs((const float4*)(in + (size_t)(r0 + r) * K_GENES + c0 + 4 * fx));
            tile[r][4 * fx + 0] = v.x;
            tile[r][4 * fx + 1] = v.y;
            tile[r][4 * fx + 2] = v.z;
            tile[r][4 * fx + 3] = v.w;
        }
    }
    __syncthreads();

    int u  = t & 7;
    int gl = t >> 3;
    #pragma unroll
    for (int p = 0; p < 2; p++) {
        int g = gl + 32 * p;
        if (c0 + g < K_GENES) {
            __half2 h0 = __floats2half2_rn(tile[8 * u + 0][g], tile[8 * u + 1][g]);
            __half2 h1 = __floats2half2_rn(tile[8 * u + 2][g], tile[8 * u + 3][g]);
            __half2 h2 = __floats2half2_rn(tile[8 * u + 4][g], tile[8 * u + 5][g]);
            __half2 h3 = __floats2half2_rn(tile[8 * u + 6][g], tile[8 * u + 7][g]);
            uint4 o;
            o.x = *(unsigned*)&h0; o.y = *(unsigned*)&h1;
            o.z = *(unsigned*)&h2; o.w = *(unsigned*)&h3;
            *(uint4*)&g_stage[(size_t)(c0 + g) * CHUNK + rl + 8 * u] = o;
        }
    }
}

// ---------------------------------------------------------------------------
// 4) fused sparse accumulation over one chunk, reading L2-resident staging.
//    Block = (32 columns, 256 batch). Lists presorted. uint4 loads -> 8 FMAs.
//    Output written evict-first (stream-once).
__global__ void spmm_chunk_kernel(float* __restrict__ out, int chunk) {
    __shared__ int   s_ei[8][CAP];
    __shared__ float s_ev[8][CAP];
    __shared__ float s_out[BT][JT + 1];

    int w     = threadIdx.x >> 5;
    int lane  = threadIdx.x & 31;
    int bl    = blockIdx.y * BT;             // batch base within chunk
    int b0    = chunk * CHUNK + bl;          // global batch base
    int jbase = blockIdx.x * JT + w * 4;

    #pragma unroll
    for (int cc = 0; cc < 4; cc++) {
        int j = jbase + cc;
        int n = 0;
        if (j < N_GO) n = min(g_cnt[j], CAP);

        for (int e = lane; e < n; e += 32) {
            s_ei[w][e] = g_ei[(size_t)j * CAP + e];
            s_ev[w][e] = g_ev[(size_t)j * CAP + e];
        }
        __syncwarp();

        float acc[8];
        #pragma unroll
        for (int q = 0; q < 8; q++) acc[q] = 0.f;

        const __half* xb = g_stage + bl + lane * 8;
        for (int e = 0; e < n; e++) {
            int   i = s_ei[w][e];
            float v = s_ev[w][e];
            uint4 u = __ldg((const uint4*)(xb + (size_t)i * CHUNK));
            float2 f0 = __half22float2(*(__half2*)&u.x);
            float2 f1 = __half22float2(*(__half2*)&u.y);
            float2 f2 = __half22float2(*(__half2*)&u.z);
            float2 f3 = __half22float2(*(__half2*)&u.w);
            acc[0] = fmaf(f0.x, v, acc[0]);
            acc[1] = fmaf(f0.y, v, acc[1]);
            acc[2] = fmaf(f1.x, v, acc[2]);
            acc[3] = fmaf(f1.y, v, acc[3]);
            acc[4] = fmaf(f2.x, v, acc[4]);
            acc[5] = fmaf(f2.y, v, acc[5]);
            acc[6] = fmaf(f3.x, v, acc[6]);
            acc[7] = fmaf(f3.y, v, acc[7]);
        }
        __syncwarp();

        #pragma unroll
        for (int q = 0; q < 8; q++) {
            s_out[lane * 8 + q][w * 4 + cc] = acc[q];
        }
    }
    __syncthreads();

    // coalesced evict-first write: 128B per row segment out[b, j0..j0+31]
    int col = threadIdx.x & 31;
    int j   = blockIdx.x * JT + col;
    if (j < N_GO) {
        #pragma unroll 4
        for (int r = threadIdx.x >> 5; r < BT; r += 8) {
            __stcs(&out[(size_t)(b0 + r) * N_GO + j], s_out[r][col]);
        }
    }
}

// ---------------------------------------------------------------------------
extern "C" void kernel_launch(void* const* d_in, const int* in_sizes, int n_in,
                              void* d_out, int out_size) {
    const float* x = (const float*)d_in[0];   // [4096, 20000]
    const float* w = (const float*)d_in[1];   // [20000, 5000]
    const float* m = (const float*)d_in[2];   // [20000, 5000]
    float* out = (float*)d_out;               // [4096, 5000]

    zero_cnt_kernel<<<(N_GO + 255) / 256, 256>>>();
    build_entries_kernel<<<4736, 256>>>(w, m);
    sort_entries_kernel<<<(N_GO + 7) / 8, 256>>>();

    dim3 tgrid((K_GENES + 63) / 64, CHUNK / 64);
    dim3 sgrid((N_GO + JT - 1) / JT, CHUNK / BT);
    for (int c = 0; c < BATCH / CHUNK; c++) {
        transpose_chunk_kernel<<<tgrid, 256>>>(x, c);
        spmm_chunk_kernel<<<sgrid, 256>>>(out, c);
    }
}